// round 3
// baseline (speedup 1.0000x reference)
#include <cuda_runtime.h>
#include <cuda_bf16.h>
#include <cstdint>

// LSTMModel: B=4096, T=512, D=8, H=64, 2 layers + FC(64->1)
//
// Design (sm_103a):
//  - 128 blocks x 256 threads. Block handles 32 batch elements, holds ALL
//    weights (transposed) in smem (~222 KB). One wave over the chip.
//  - Thread layout: group g = tid>>6 (4 groups), unit j = tid&63.
//    Thread computes the 4 gate rows of hidden unit j for 8 batch elements
//    (4 batch-pairs packed as f32x2), for both layers.
//  - Inner product uses fma.rn.f32x2 (FFMA2) -> 128 FMA/cyc/SM.
//  - Weights layout in smem: W[k][j*4+gate]  -> one LDS.128 per thread per k.
//    h state layout: h[k][pair] (row stride 36 floats, padded) -> broadcast
//    LDS.128 reads, modest-conflict writes.
//  - Activations: sigmoid/tanh from ex2.approx + rcp.approx (accurate enough).

#define ULL unsigned long long

static __device__ __forceinline__ ULL pk2(float v) {
    ULL r; asm("mov.b64 %0, {%1, %1};" : "=l"(r) : "f"(v)); return r;
}
static __device__ __forceinline__ ULL pkf2(float a, float b) {
    ULL r; asm("mov.b64 %0, {%1, %2};" : "=l"(r) : "f"(a), "f"(b)); return r;
}
static __device__ __forceinline__ float2 upk(ULL v) {
    float2 f; asm("mov.b64 {%0, %1}, %2;" : "=f"(f.x), "=f"(f.y) : "l"(v)); return f;
}
static __device__ __forceinline__ ULL ffma2(ULL a, ULL b, ULL c) {
    ULL d; asm("fma.rn.f32x2 %0, %1, %2, %3;" : "=l"(d) : "l"(a), "l"(b), "l"(c)); return d;
}
static __device__ __forceinline__ float ex2f(float x) {
    float r; asm("ex2.approx.f32 %0, %1;" : "=f"(r) : "f"(x)); return r;
}
static __device__ __forceinline__ float rcpf(float x) {
    float r; asm("rcp.approx.f32 %0, %1;" : "=f"(r) : "f"(x)); return r;
}
static __device__ __forceinline__ float sigm(float x) {
    // 1/(1+e^-x); safe for all x (overflow -> rcp(inf)=0)
    return rcpf(1.0f + ex2f(-1.4426950408889634f * x));
}
static __device__ __forceinline__ float tanh_fast(float x) {
    // tanh(|x|) = (1-p)/(1+p), p = e^{-2|x|} in (0,1]; restore sign.
    float ax = fabsf(x);
    float p = ex2f(-2.8853900817779268f * ax);
    float r = (1.0f - p) * rcpf(1.0f + p);
    return copysignf(r, x);
}

static constexpr int B = 4096;
static constexpr int T = 512;
static constexpr int D = 8;
static constexpr int NBATCH_BLK = 32;   // batch per block
static constexpr int NGROUP = 4;        // groups of 64 threads
static constexpr int HSTRIDE = 36;      // padded row stride (floats) for h state

// smem float offsets
static constexpr int OFF_WIH0 = 0;                    //  8*256
static constexpr int OFF_WHH0 = OFF_WIH0 + 2048;      // 64*256
static constexpr int OFF_WIH1 = OFF_WHH0 + 16384;     // 64*256
static constexpr int OFF_WHH1 = OFF_WIH1 + 16384;     // 64*256
static constexpr int OFF_B0   = OFF_WHH1 + 16384;     // 256
static constexpr int OFF_B1   = OFF_B0 + 256;         // 256
static constexpr int OFF_WFC  = OFF_B1 + 256;         // 64
static constexpr int OFF_H0   = OFF_WFC + 64;         // 64*36
static constexpr int OFF_H1   = OFF_H0 + 64 * HSTRIDE;// 64*36
static constexpr int OFF_XS   = OFF_H1 + 64 * HSTRIDE;// 2*256
static constexpr int SMEM_FLOATS = OFF_XS + 512;
static constexpr int SMEM_BYTES = SMEM_FLOATS * 4;    // 227,584 B

// Accumulate 4 gates x 4 pairs from one k-slice.
// wrow: &W[k][j*4]   hrow: 4 pairs (32B, 16B-aligned)
#define ACC_STEP(wbase, hbase)                                              \
    do {                                                                    \
        float4 w = *(const float4*)(wbase);                                 \
        ulonglong2 hA = *(const ulonglong2*)(hbase);                        \
        ulonglong2 hB = *(const ulonglong2*)((const float*)(hbase) + 4);    \
        ULL w0 = pk2(w.x), w1 = pk2(w.y), w2 = pk2(w.z), w3 = pk2(w.w);     \
        a00 = ffma2(w0, hA.x, a00); a01 = ffma2(w0, hA.y, a01);             \
        a02 = ffma2(w0, hB.x, a02); a03 = ffma2(w0, hB.y, a03);             \
        a10 = ffma2(w1, hA.x, a10); a11 = ffma2(w1, hA.y, a11);             \
        a12 = ffma2(w1, hB.x, a12); a13 = ffma2(w1, hB.y, a13);             \
        a20 = ffma2(w2, hA.x, a20); a21 = ffma2(w2, hA.y, a21);             \
        a22 = ffma2(w2, hB.x, a22); a23 = ffma2(w2, hB.y, a23);             \
        a30 = ffma2(w3, hA.x, a30); a31 = ffma2(w3, hA.y, a31);             \
        a32 = ffma2(w3, hB.x, a32); a33 = ffma2(w3, hB.y, a33);             \
    } while (0)

// Per-pair LSTM cell update. zi,zf,zg,zo: packed gate pre-activations.
// c: packed cell state (in/out). Returns packed h.
static __device__ __forceinline__ ULL cell_update(ULL zi, ULL zf, ULL zg, ULL zo, ULL& c) {
    float2 i2 = upk(zi), f2 = upk(zf), g2 = upk(zg), o2 = upk(zo), c2 = upk(c);
    float i0 = sigm(i2.x), f0 = sigm(f2.x), g0 = tanh_fast(g2.x), o0 = sigm(o2.x);
    float i1 = sigm(i2.y), f1 = sigm(f2.y), g1 = tanh_fast(g2.y), o1 = sigm(o2.y);
    float cn0 = f0 * c2.x + i0 * g0;
    float cn1 = f1 * c2.y + i1 * g1;
    c = pkf2(cn0, cn1);
    float h0 = o0 * tanh_fast(cn0);
    float h1 = o1 * tanh_fast(cn1);
    return pkf2(h0, h1);
}

extern __shared__ float sm[];

__global__ void __launch_bounds__(256, 1)
lstm_kernel(const float* __restrict__ x,
            const float* __restrict__ Wih0, const float* __restrict__ Whh0,
            const float* __restrict__ bih0, const float* __restrict__ bhh0,
            const float* __restrict__ Wih1, const float* __restrict__ Whh1,
            const float* __restrict__ bih1, const float* __restrict__ bhh1,
            const float* __restrict__ Wfc,  const float* __restrict__ bfc,
            float* __restrict__ out)
{
    const int tid = threadIdx.x;
    const int j = tid & 63;        // hidden unit
    const int g = tid >> 6;        // group (0..3): batch 8g..8g+7
    const int Bb = blockIdx.x * NBATCH_BLK;

    // ---- load + transpose weights into smem ----
    // layout: W[k][j*4 + gate] = Wglobal[gate*64 + j][k]
    for (int idx = tid; idx < 2048; idx += 256) {
        int d = idx >> 8, r = idx & 255, jj = r >> 2, q = r & 3;
        sm[OFF_WIH0 + idx] = Wih0[(q * 64 + jj) * 8 + d];
    }
    for (int idx = tid; idx < 16384; idx += 256) {
        int k = idx >> 8, r = idx & 255, jj = r >> 2, q = r & 3;
        int row = (q * 64 + jj) * 64 + k;
        sm[OFF_WHH0 + idx] = Whh0[row];
        sm[OFF_WIH1 + idx] = Wih1[row];
        sm[OFF_WHH1 + idx] = Whh1[row];
    }
    {
        int jj = tid >> 2, q = tid & 3;
        sm[OFF_B0 + tid] = bih0[q * 64 + jj] + bhh0[q * 64 + jj];
        sm[OFF_B1 + tid] = bih1[q * 64 + jj] + bhh1[q * 64 + jj];
    }
    if (tid < 64) sm[OFF_WFC + tid] = Wfc[tid];
    for (int idx = tid; idx < 2 * 64 * HSTRIDE; idx += 256)
        sm[OFF_H0 + idx] = 0.0f;   // zero h0 and h1 (contiguous regions)

    // x prefetch mapping: thread loads x[Bb + bl][t][dl]
    const int bl = tid >> 3;       // 0..31
    const int dl = tid & 7;        // 0..7
    const float* xptr = x + (size_t)(Bb + bl) * (T * D) + dl;
    // stage layout: xs[buf][d*32 + b_local]
    float x0 = __ldg(xptr);        // t = 0
    __syncthreads();
    sm[OFF_XS + dl * 32 + bl] = x0;

    // cell state, packed pairs (unit j, 4 pairs = 8 batch)
    ULL c0p0 = 0, c0p1 = 0, c0p2 = 0, c0p3 = 0;
    ULL c1p0 = 0, c1p1 = 0, c1p2 = 0, c1p3 = 0;

    const float* b0v = sm + OFF_B0 + j * 4;
    const float* b1v = sm + OFF_B1 + j * 4;
    const int hoff = g * 8;          // float offset of this group's 4 pairs
    float* h0dst = sm + OFF_H0 + j * HSTRIDE + hoff;
    float* h1dst = sm + OFF_H1 + j * HSTRIDE + hoff;

    __syncthreads();   // x stage for t=0 visible

    for (int t = 0; t < T; ++t) {
        const int cur = (t & 1) * 256;
        const int nxt = 256 - cur;
        // prefetch next timestep's x
        float xn = 0.0f;
        if (t + 1 < T) xn = __ldg(xptr + (t + 1) * D);

        // ---------- layer 0 gates ----------
        ULL a00, a01, a02, a03, a10, a11, a12, a13;
        ULL a20, a21, a22, a23, a30, a31, a32, a33;
        {
            float4 b4 = *(const float4*)b0v;
            a00 = a01 = a02 = a03 = pk2(b4.x);
            a10 = a11 = a12 = a13 = pk2(b4.y);
            a20 = a21 = a22 = a23 = pk2(b4.z);
            a30 = a31 = a32 = a33 = pk2(b4.w);
        }
        // x projection (D=8)
        #pragma unroll
        for (int d = 0; d < D; ++d)
            ACC_STEP(sm + OFF_WIH0 + d * 256 + j * 4, sm + OFF_XS + cur + d * 32 + hoff);
        // h0_{t-1} @ Whh0^T
        #pragma unroll 8
        for (int k = 0; k < 64; ++k)
            ACC_STEP(sm + OFF_WHH0 + k * 256 + j * 4, sm + OFF_H0 + k * HSTRIDE + hoff);

        __syncthreads();   // all reads of h0s(old) done

        {
            ULL h0 = cell_update(a00, a10, a20, a30, c0p0);
            ULL h1 = cell_update(a01, a11, a21, a31, c0p1);
            ULL h2 = cell_update(a02, a12, a22, a32, c0p2);
            ULL h3 = cell_update(a03, a13, a23, a33, c0p3);
            *(ulonglong2*)(h0dst) = make_ulonglong2(h0, h1);
            *(ulonglong2*)(h0dst + 4) = make_ulonglong2(h2, h3);
        }

        __syncthreads();   // h0s(new) visible

        // ---------- layer 1 gates ----------
        {
            float4 b4 = *(const float4*)b1v;
            a00 = a01 = a02 = a03 = pk2(b4.x);
            a10 = a11 = a12 = a13 = pk2(b4.y);
            a20 = a21 = a22 = a23 = pk2(b4.z);
            a30 = a31 = a32 = a33 = pk2(b4.w);
        }
        #pragma unroll 8
        for (int k = 0; k < 64; ++k)
            ACC_STEP(sm + OFF_WIH1 + k * 256 + j * 4, sm + OFF_H0 + k * HSTRIDE + hoff);
        #pragma unroll 8
        for (int k = 0; k < 64; ++k)
            ACC_STEP(sm + OFF_WHH1 + k * 256 + j * 4, sm + OFF_H1 + k * HSTRIDE + hoff);

        __syncthreads();   // all reads of h1s(old) done

        {
            ULL h0 = cell_update(a00, a10, a20, a30, c1p0);
            ULL h1 = cell_update(a01, a11, a21, a31, c1p1);
            ULL h2 = cell_update(a02, a12, a22, a32, c1p2);
            ULL h3 = cell_update(a03, a13, a23, a33, c1p3);
            *(ulonglong2*)(h1dst) = make_ulonglong2(h0, h1);
            *(ulonglong2*)(h1dst + 4) = make_ulonglong2(h2, h3);
        }
        // stage x for next step (double-buffered; readers of 'nxt' finished
        // before sync1 of the previous iteration)
        sm[OFF_XS + nxt + dl * 32 + bl] = xn;

        __syncthreads();   // h1s(new) + xs(next) visible
    }

    // ---------- FC head: out[b] = h1[b] . Wfc + bfc ----------
    if (tid < NBATCH_BLK) {
        float acc = __ldg(bfc);
        #pragma unroll 8
        for (int k = 0; k < 64; ++k)
            acc += sm[OFF_H1 + k * HSTRIDE + tid] * sm[OFF_WFC + k];
        out[Bb + tid] = acc;
    }
}

extern "C" void kernel_launch(void* const* d_in, const int* in_sizes, int n_in,
                              void* d_out, int out_size) {
    (void)in_sizes; (void)n_in; (void)out_size;
    const float* x    = (const float*)d_in[0];
    const float* Wih0 = (const float*)d_in[1];
    const float* Whh0 = (const float*)d_in[2];
    const float* bih0 = (const float*)d_in[3];
    const float* bhh0 = (const float*)d_in[4];
    const float* Wih1 = (const float*)d_in[5];
    const float* Whh1 = (const float*)d_in[6];
    const float* bih1 = (const float*)d_in[7];
    const float* bhh1 = (const float*)d_in[8];
    const float* Wfc  = (const float*)d_in[9];
    const float* bfc  = (const float*)d_in[10];
    float* out = (float*)d_out;

    cudaFuncSetAttribute(lstm_kernel,
                         cudaFuncAttributeMaxDynamicSharedMemorySize, SMEM_BYTES);
    lstm_kernel<<<B / NBATCH_BLK, 256, SMEM_BYTES>>>(
        x, Wih0, Whh0, bih0, bhh0, Wih1, Whh1, bih1, bhh1, Wfc, bfc, out);
}